// round 2
// baseline (speedup 1.0000x reference)
#include <cuda_runtime.h>
#include <cuda_bf16.h>
#include <math.h>

// ----------------------------------------------------------------------------
// MultiScaleDecoder: all layers are GEMMs with fused scatter epilogues.
//   n = B*H*W = 16384 pixel patches
//   L1: relu(input_s[16384,512] @ dense_w[512,512] + b) -> scatter into X1[65536,384]
//       (X1 row = n*4 + (a*2+c), col = s*128 + k)
//   L2: relu(X1[65536,384] @ w1^T[384,256] + b1) -> scatter into X2[262144,64]
//   L3: relu(X2[262144,64] @ w2^T[64,128] + b2) -> scatter into X3[1048576,32]
//   L4: sigmoid(X3 @ w3^T[32,12] + b3) -> scatter into out[16384,16,16,3]
// ----------------------------------------------------------------------------

#define N_PATCH   16384
#define X1_ROWS   (N_PATCH * 4)       // 65536
#define X2_ROWS   (N_PATCH * 16)     // 262144
#define X3_ROWS   (N_PATCH * 64)     // 1048576

__device__ float g_X1[(size_t)X1_ROWS * 384];   // 100.7 MB
__device__ float g_X2[(size_t)X2_ROWS * 64];    //  67.1 MB
__device__ float g_X3[(size_t)X3_ROWS * 32];    // 134.2 MB

// ----------------------------------------------------------------------------
// Tiled SGEMM: BM=128, BN=128, BK=8, 256 threads, 8x8 per-thread tile.
// BT=true  -> B is [N,K] row-major (A @ B^T)
// BT=false -> B is [K,N] row-major (A @ B)
// EPI selects bias indexing + activation + scatter address.
// All dims are exact multiples of the tile sizes for this problem.
// ----------------------------------------------------------------------------
template <bool BT, int EPI>
__global__ __launch_bounds__(256)
void gemm_epi(const float* __restrict__ A, const float* __restrict__ B,
              const float* __restrict__ bias, float* __restrict__ Out,
              int M, int N, int K, int s)
{
    __shared__ float As[8][128];
    __shared__ float Bs[8][128];

    const int tid  = threadIdx.x;
    const int row0 = blockIdx.y * 128;
    const int col0 = blockIdx.x * 128;

    // A (and B-transposed) load pattern: 128 rows x 8 cols, one float4/thread
    const int lrow = tid >> 1;          // 0..127
    const int lcol = (tid & 1) * 4;     // 0 or 4
    // B non-transposed load pattern: 8 rows x 128 cols
    const int brow = tid >> 5;          // 0..7
    const int bcol = (tid & 31) * 4;    // 0..124

    const int ty = tid >> 4;            // 0..15 -> row block
    const int tx = tid & 15;            // 0..15 -> col block

    float acc[8][8];
    #pragma unroll
    for (int i = 0; i < 8; i++)
        #pragma unroll
        for (int j = 0; j < 8; j++) acc[i][j] = 0.f;

    for (int k0 = 0; k0 < K; k0 += 8) {
        float4 av = *reinterpret_cast<const float4*>(
            &A[(size_t)(row0 + lrow) * K + k0 + lcol]);
        As[lcol + 0][lrow] = av.x;
        As[lcol + 1][lrow] = av.y;
        As[lcol + 2][lrow] = av.z;
        As[lcol + 3][lrow] = av.w;

        if (BT) {
            float4 bv = *reinterpret_cast<const float4*>(
                &B[(size_t)(col0 + lrow) * K + k0 + lcol]);
            Bs[lcol + 0][lrow] = bv.x;
            Bs[lcol + 1][lrow] = bv.y;
            Bs[lcol + 2][lrow] = bv.z;
            Bs[lcol + 3][lrow] = bv.w;
        } else {
            float4 bv = *reinterpret_cast<const float4*>(
                &B[(size_t)(k0 + brow) * N + col0 + bcol]);
            *reinterpret_cast<float4*>(&Bs[brow][bcol]) = bv;
        }
        __syncthreads();

        #pragma unroll
        for (int kk = 0; kk < 8; kk++) {
            float af[8], bf[8];
            #pragma unroll
            for (int i = 0; i < 8; i++) af[i] = As[kk][ty * 8 + i];
            #pragma unroll
            for (int j = 0; j < 8; j++) bf[j] = Bs[kk][tx * 8 + j];
            #pragma unroll
            for (int i = 0; i < 8; i++)
                #pragma unroll
                for (int j = 0; j < 8; j++)
                    acc[i][j] = fmaf(af[i], bf[j], acc[i][j]);
        }
        __syncthreads();
    }

    // Epilogue: bias + relu + scatter
    #pragma unroll
    for (int i = 0; i < 8; i++) {
        const int row = row0 + ty * 8 + i;
        #pragma unroll
        for (int j = 0; j < 8; j++) {
            const int col = col0 + tx * 8 + j;
            float b;
            if (EPI == 1)       b = bias[col];
            else if (EPI == 2)  b = bias[col & 63];
            else                b = bias[col & 31];
            float v = fmaxf(acc[i][j] + b, 0.f);

            size_t addr;
            if (EPI == 1) {
                // dense: D[n, (a*2+c)*128 + k] -> X1[n*4 + pos][s*128 + k]
                const int pos = col >> 7, kc = col & 127;
                addr = ((size_t)(row * 4 + pos)) * 384 + s * 128 + kc;
            } else if (EPI == 2) {
                // deconv1: row=(n,i,j) col=(a,c,f) -> X2[n*16+(2i+a)*4+(2j+c)][f]
                const int a = col >> 7, c = (col >> 6) & 1, f = col & 63;
                const int nn = row >> 2, ii = (row >> 1) & 1, jj = row & 1;
                addr = ((size_t)(nn * 16 + (2 * ii + a) * 4 + (2 * jj + c))) * 64 + f;
            } else {
                // deconv2: row=(n,p,q) col=(a,c,f) -> X3[n*64+(2p+a)*8+(2q+c)][f]
                const int a = col >> 6, c = (col >> 5) & 1, f = col & 31;
                const int nn = row >> 4, p = (row >> 2) & 3, q = row & 3;
                addr = ((size_t)(nn * 64 + (2 * p + a) * 8 + (2 * q + c))) * 32 + f;
            }
            Out[addr] = v;
        }
    }
}

// ----------------------------------------------------------------------------
// Layer 4: X3[1048576, 32] @ w3^T[32,12] + b3, sigmoid, scatter to
// out[n,16,16,3]. One thread per row; w3 in smem.
// ----------------------------------------------------------------------------
__global__ __launch_bounds__(256)
void layer4_kernel(const float* __restrict__ X3, const float* __restrict__ w3,
                   const float* __restrict__ b3, float* __restrict__ out)
{
    __shared__ float ws[12 * 32];   // w3 flat: ((a*2+c)*3+ch)*32 + k = o*32 + k
    __shared__ float bs[3];
    for (int i = threadIdx.x; i < 384; i += 256) ws[i] = w3[i];   // FIX: 384 > blockDim
    if (threadIdx.x < 3) bs[threadIdx.x] = b3[threadIdx.x];
    __syncthreads();

    const int r = blockIdx.x * 256 + threadIdx.x;   // 0 .. 1048575

    float x[32];
    const float4* xp = reinterpret_cast<const float4*>(X3 + (size_t)r * 32);
    #pragma unroll
    for (int i = 0; i < 8; i++) {
        float4 v = xp[i];
        x[4 * i + 0] = v.x; x[4 * i + 1] = v.y;
        x[4 * i + 2] = v.z; x[4 * i + 3] = v.w;
    }

    const int n = r >> 6, p = (r >> 3) & 7, q = r & 7;
    const size_t base = (size_t)n * 768;

    #pragma unroll
    for (int o = 0; o < 12; o++) {
        float acc = bs[o % 3];
        #pragma unroll
        for (int k = 0; k < 32; k++) acc = fmaf(x[k], ws[o * 32 + k], acc);
        const float v = 1.f / (1.f + expf(-acc));
        const int a = o / 6, c = (o / 3) & 1, ch = o % 3;
        out[base + (2 * p + a) * 48 + (2 * q + c) * 3 + ch] = v;
    }
}

// ----------------------------------------------------------------------------
// Host entry
// ----------------------------------------------------------------------------
extern "C" void kernel_launch(void* const* d_in, const int* in_sizes, int n_in,
                              void* d_out, int out_size)
{
    const float* in1     = (const float*)d_in[0];
    const float* in2     = (const float*)d_in[1];
    const float* in3     = (const float*)d_in[2];
    const float* dense_w = (const float*)d_in[3];
    const float* dense_b = (const float*)d_in[4];
    const float* w1      = (const float*)d_in[5];
    const float* b1      = (const float*)d_in[6];
    const float* w2      = (const float*)d_in[7];
    const float* b2      = (const float*)d_in[8];
    const float* w3      = (const float*)d_in[9];
    const float* b3      = (const float*)d_in[10];
    float* out           = (float*)d_out;

    float *x1, *x2, *x3;
    cudaGetSymbolAddress((void**)&x1, g_X1);
    cudaGetSymbolAddress((void**)&x2, g_X2);
    cudaGetSymbolAddress((void**)&x3, g_X3);

    // L1: three dense GEMMs (shared weights), scatter into X1 with concat layout
    {
        dim3 grid(512 / 128, N_PATCH / 128);
        gemm_epi<false, 1><<<grid, 256>>>(in1, dense_w, dense_b, x1,
                                          N_PATCH, 512, 512, 0);
        gemm_epi<false, 1><<<grid, 256>>>(in2, dense_w, dense_b, x1,
                                          N_PATCH, 512, 512, 1);
        gemm_epi<false, 1><<<grid, 256>>>(in3, dense_w, dense_b, x1,
                                          N_PATCH, 512, 512, 2);
    }
    // L2: [65536,384] @ w1^T[384,256]
    {
        dim3 grid(256 / 128, X1_ROWS / 128);
        gemm_epi<true, 2><<<grid, 256>>>(x1, w1, b1, x2,
                                         X1_ROWS, 256, 384, 0);
    }
    // L3: [262144,64] @ w2^T[64,128]
    {
        dim3 grid(128 / 128, X2_ROWS / 128);
        gemm_epi<true, 3><<<grid, 256>>>(x2, w2, b2, x3,
                                         X2_ROWS, 128, 64, 0);
    }
    // L4: sigmoid head, one thread per X3 row
    layer4_kernel<<<X3_ROWS / 256, 256>>>(x3, w3, b3, out);
}

// round 3
// speedup vs baseline: 5.6284x; 5.6284x over previous
#include <cuda_runtime.h>
#include <cuda_bf16.h>
#include <math.h>
#include <stdint.h>

// ----------------------------------------------------------------------------
// MultiScaleDecoder, tensor-core version (mma.sync bf16, fp32 accum).
//   n = B*H*W = 16384 patches
//   prepass: inputs fp32 -> bf16 (one [49152,512] A matrix), weights -> bf16
//   L1: relu(A @ Wd^T)  M=49152 N=512 K=512 -> scatter X1[65536,384] bf16
//   L2: relu(X1 @ w1^T) M=65536 N=256 K=384 -> scatter X2[262144,64] bf16
//   L3: relu(X2 @ w2^T) M=262144 N=128 K=64 -> scatter X3[1048576,32] bf16
//   L4: sigmoid(X3 @ w3^T + b3) -> out[16384,16,16,3] fp32
// ----------------------------------------------------------------------------

#define NP 16384
#define L1_M (3 * NP)                 // 49152
#define X1_ROWS (NP * 4)              // 65536
#define X2_ROWS (NP * 16)             // 262144
#define X3_ROWS (NP * 64)             // 1048576

__device__ __nv_bfloat16 g_Ain[(size_t)L1_M * 512];    // 50.3 MB
__device__ __nv_bfloat16 g_X1[(size_t)X1_ROWS * 384];  // 50.3 MB
__device__ __nv_bfloat16 g_X2[(size_t)X2_ROWS * 64];   // 33.6 MB
__device__ __nv_bfloat16 g_X3[(size_t)X3_ROWS * 32];   // 67.1 MB
__device__ __nv_bfloat16 g_Wd[512 * 512];              // [n][k]
__device__ __nv_bfloat16 g_W1[256 * 384];              // [n][k]
__device__ __nv_bfloat16 g_W2[128 * 64];               // [n][k]

// ---------------------------------------------------------------- prepasses
__global__ __launch_bounds__(256) void f2bf(const float* __restrict__ src,
                                            __nv_bfloat16* __restrict__ dst,
                                            int n) {
    int i = (blockIdx.x * 256 + threadIdx.x) * 4;
    if (i < n) {
        float4 v = *reinterpret_cast<const float4*>(src + i);
        *reinterpret_cast<__nv_bfloat162*>(dst + i)     = __floats2bfloat162_rn(v.x, v.y);
        *reinterpret_cast<__nv_bfloat162*>(dst + i + 2) = __floats2bfloat162_rn(v.z, v.w);
    }
}

// dense_w [k=512][n=512] -> g_Wd [n][k] bf16
__global__ void transpose_w(const float* __restrict__ src,
                            __nv_bfloat16* __restrict__ dst) {
    __shared__ float t[32][33];
    int k0 = blockIdx.y * 32, n0 = blockIdx.x * 32;
    int tx = threadIdx.x, ty = threadIdx.y;  // block (32, 8)
    for (int r = ty; r < 32; r += 8) t[r][tx] = src[(k0 + r) * 512 + n0 + tx];
    __syncthreads();
    for (int r = ty; r < 32; r += 8)
        dst[(size_t)(n0 + r) * 512 + k0 + tx] = __float2bfloat16(t[tx][r]);
}

// ---------------------------------------------------------------- mma utils
__device__ __forceinline__ uint32_t smem_u32(const void* p) {
    return (uint32_t)__cvta_generic_to_shared(p);
}
__device__ __forceinline__ void ldsm4(uint32_t& r0, uint32_t& r1, uint32_t& r2,
                                      uint32_t& r3, uint32_t addr) {
    asm volatile("ldmatrix.sync.aligned.m8n8.x4.shared.b16 {%0,%1,%2,%3}, [%4];\n"
                 : "=r"(r0), "=r"(r1), "=r"(r2), "=r"(r3) : "r"(addr));
}
__device__ __forceinline__ void mma16816(float* c, const uint32_t* a,
                                         const uint32_t* b) {
    asm volatile(
        "mma.sync.aligned.m16n8k16.row.col.f32.bf16.bf16.f32 "
        "{%0,%1,%2,%3}, {%4,%5,%6,%7}, {%8,%9}, {%0,%1,%2,%3};\n"
        : "+f"(c[0]), "+f"(c[1]), "+f"(c[2]), "+f"(c[3])
        : "r"(a[0]), "r"(a[1]), "r"(a[2]), "r"(a[3]), "r"(b[0]), "r"(b[1]));
}
__device__ __forceinline__ void cp16(void* sdst, const void* gsrc) {
    asm volatile("cp.async.cg.shared.global [%0], [%1], 16;\n" ::
                 "r"(smem_u32(sdst)), "l"(gsrc));
}

#define BM 128
#define BN 128
#define BK 32
#define LDP 40  // padded smem row (elems): 80B stride -> conflict-free ldmatrix

// ---------------------------------------------------------------- GEMM + scatter
template <int EPI>
__global__ __launch_bounds__(256)
void mma_gemm(const __nv_bfloat16* __restrict__ A,
              const __nv_bfloat16* __restrict__ B,
              const float* __restrict__ bias,
              __nv_bfloat16* __restrict__ Out, int M, int N, int K)
{
    __shared__ __align__(16) __nv_bfloat16 As[2][BM * LDP];
    __shared__ __align__(16) __nv_bfloat16 Bs[2][BN * LDP];

    const int tid = threadIdx.x;
    const int warp = tid >> 5, lane = tid & 31;
    const int row0 = blockIdx.y * BM;
    const int col0 = blockIdx.x * BN;
    const int wm = (warp >> 2) * 64;   // warp tile 64x32
    const int wn = (warp & 3) * 32;

    const int NIT = K / BK;

    auto load_stage = [&](int buf, int ko) {
        #pragma unroll
        for (int c = 0; c < 2; c++) {
            int ch = tid + c * 256;            // 0..511
            int r = ch >> 2, cc = (ch & 3) * 8;
            cp16(&As[buf][r * LDP + cc], &A[(size_t)(row0 + r) * K + ko + cc]);
        }
        #pragma unroll
        for (int c = 0; c < 2; c++) {
            int ch = tid + c * 256;
            int r = ch >> 2, cc = (ch & 3) * 8;
            cp16(&Bs[buf][r * LDP + cc], &B[(size_t)(col0 + r) * K + ko + cc]);
        }
        asm volatile("cp.async.commit_group;\n");
    };

    float acc[4][4][4];
    #pragma unroll
    for (int i = 0; i < 4; i++)
        #pragma unroll
        for (int j = 0; j < 4; j++)
            #pragma unroll
            for (int q = 0; q < 4; q++) acc[i][j][q] = 0.f;

    load_stage(0, 0);

    for (int it = 0; it < NIT; it++) {
        if (it + 1 < NIT) {
            load_stage((it + 1) & 1, (it + 1) * BK);
            asm volatile("cp.async.wait_group 1;\n");
        } else {
            asm volatile("cp.async.wait_group 0;\n");
        }
        __syncthreads();

        const int sb = it & 1;
        #pragma unroll
        for (int ks = 0; ks < 2; ks++) {
            const int k0 = ks * 16;
            uint32_t a[4][4], b[4][2];
            #pragma unroll
            for (int i = 0; i < 4; i++) {
                int r = wm + i * 16 + (lane & 15);
                int kk = k0 + ((lane >> 4) << 3);
                ldsm4(a[i][0], a[i][1], a[i][2], a[i][3],
                      smem_u32(&As[sb][r * LDP + kk]));
            }
            #pragma unroll
            for (int jp = 0; jp < 2; jp++) {
                // matrices: (n0..+7,k0), (n0..+7,k0+8), (n0+8..+15,k0), (n0+8..+15,k0+8)
                int rB = wn + jp * 16 + ((lane >> 4) << 3) + (lane & 7);
                int kk = k0 + (((lane >> 3) & 1) << 3);
                ldsm4(b[2 * jp][0], b[2 * jp][1], b[2 * jp + 1][0], b[2 * jp + 1][1],
                      smem_u32(&Bs[sb][rB * LDP + kk]));
            }
            #pragma unroll
            for (int i = 0; i < 4; i++)
                #pragma unroll
                for (int j = 0; j < 4; j++) mma16816(acc[i][j], a[i], b[j]);
        }
        __syncthreads();
    }

    // ---------------- epilogue: bias + relu + scatter, bf162 pair stores
    auto epi_store = [&](int row, int col, float v0, float v1) {
        float b0, b1;
        if (EPI == 1)      { b0 = bias[col];      b1 = bias[col + 1]; }
        else if (EPI == 2) { b0 = bias[col & 63]; b1 = bias[(col & 63) + 1]; }
        else               { b0 = bias[col & 31]; b1 = bias[(col & 31) + 1]; }
        v0 = fmaxf(v0 + b0, 0.f);
        v1 = fmaxf(v1 + b1, 0.f);
        size_t addr;
        if (EPI == 1) {
            const int pos = col >> 7, kc = col & 127;
            const int s = row >> 14, nl = row & (NP - 1);
            addr = ((size_t)(nl * 4 + pos)) * 384 + s * 128 + kc;
        } else if (EPI == 2) {
            const int a_ = col >> 7, c_ = (col >> 6) & 1, f = col & 63;
            const int nn = row >> 2, ii = (row >> 1) & 1, jj = row & 1;
            addr = ((size_t)(nn * 16 + (2 * ii + a_) * 4 + (2 * jj + c_))) * 64 + f;
        } else {
            const int a_ = col >> 6, c_ = (col >> 5) & 1, f = col & 31;
            const int nn = row >> 4, p = (row >> 2) & 3, q = row & 3;
            addr = ((size_t)(nn * 64 + (2 * p + a_) * 8 + (2 * q + c_))) * 32 + f;
        }
        *reinterpret_cast<__nv_bfloat162*>(&Out[addr]) = __floats2bfloat162_rn(v0, v1);
    };

    #pragma unroll
    for (int i = 0; i < 4; i++) {
        const int mA = row0 + wm + i * 16 + (lane >> 2);
        #pragma unroll
        for (int j = 0; j < 4; j++) {
            const int nA = col0 + wn + j * 8 + 2 * (lane & 3);
            epi_store(mA,     nA, acc[i][j][0], acc[i][j][1]);
            epi_store(mA + 8, nA, acc[i][j][2], acc[i][j][3]);
        }
    }
}

// ---------------------------------------------------------------- layer 4
__global__ __launch_bounds__(256)
void layer4_kernel(const __nv_bfloat16* __restrict__ X3,
                   const float* __restrict__ w3, const float* __restrict__ b3,
                   float* __restrict__ out)
{
    __shared__ float ws[12 * 32];
    __shared__ float bs[3];
    for (int i = threadIdx.x; i < 384; i += 256) ws[i] = w3[i];
    if (threadIdx.x < 3) bs[threadIdx.x] = b3[threadIdx.x];
    __syncthreads();

    const int r = blockIdx.x * 256 + threadIdx.x;  // 0 .. 1048575

    __nv_bfloat162 xr[16];
    const uint4* xp = reinterpret_cast<const uint4*>(X3 + (size_t)r * 32);
    #pragma unroll
    for (int i = 0; i < 4; i++) *reinterpret_cast<uint4*>(&xr[i * 4]) = xp[i];
    float x[32];
    #pragma unroll
    for (int i = 0; i < 16; i++) {
        float2 f = __bfloat1622float2(xr[i]);
        x[2 * i] = f.x; x[2 * i + 1] = f.y;
    }

    const int n = r >> 6, p = (r >> 3) & 7, q = r & 7;
    const size_t base = (size_t)n * 768;

    #pragma unroll
    for (int o = 0; o < 12; o++) {
        float acc = bs[o % 3];
        #pragma unroll
        for (int k = 0; k < 32; k++) acc = fmaf(x[k], ws[o * 32 + k], acc);
        const float v = 1.f / (1.f + expf(-acc));
        const int a = o / 6, c = (o / 3) & 1, ch = o % 3;
        out[base + (2 * p + a) * 48 + (2 * q + c) * 3 + ch] = v;
    }
}

// ---------------------------------------------------------------- host entry
extern "C" void kernel_launch(void* const* d_in, const int* in_sizes, int n_in,
                              void* d_out, int out_size)
{
    const float* in1     = (const float*)d_in[0];
    const float* in2     = (const float*)d_in[1];
    const float* in3     = (const float*)d_in[2];
    const float* dense_w = (const float*)d_in[3];
    const float* dense_b = (const float*)d_in[4];
    const float* w1      = (const float*)d_in[5];
    const float* b1      = (const float*)d_in[6];
    const float* w2      = (const float*)d_in[7];
    const float* b2      = (const float*)d_in[8];
    const float* w3      = (const float*)d_in[9];
    const float* b3      = (const float*)d_in[10];
    float* out           = (float*)d_out;

    __nv_bfloat16 *ain, *x1, *x2, *x3, *wd, *w1b, *w2b;
    cudaGetSymbolAddress((void**)&ain, g_Ain);
    cudaGetSymbolAddress((void**)&x1, g_X1);
    cudaGetSymbolAddress((void**)&x2, g_X2);
    cudaGetSymbolAddress((void**)&x3, g_X3);
    cudaGetSymbolAddress((void**)&wd, g_Wd);
    cudaGetSymbolAddress((void**)&w1b, g_W1);
    cudaGetSymbolAddress((void**)&w2b, g_W2);

    const int NIN = NP * 512;  // 8388608 per input
    f2bf<<<NIN / 1024, 256>>>(in1, ain, NIN);
    f2bf<<<NIN / 1024, 256>>>(in2, ain + (size_t)NIN, NIN);
    f2bf<<<NIN / 1024, 256>>>(in3, ain + (size_t)2 * NIN, NIN);
    transpose_w<<<dim3(16, 16), dim3(32, 8)>>>(dense_w, wd);
    f2bf<<<(256 * 384) / 1024, 256>>>(w1, w1b, 256 * 384);
    f2bf<<<(128 * 64) / 1024, 256>>>(w2, w2b, 128 * 64);

    // L1: [49152,512] @ Wd^T[512,512]
    mma_gemm<1><<<dim3(512 / BN, L1_M / BM), 256>>>(ain, wd, dense_b, x1,
                                                    L1_M, 512, 512);
    // L2: [65536,384] @ w1^T[384,256]
    mma_gemm<2><<<dim3(256 / BN, X1_ROWS / BM), 256>>>(x1, w1b, b1, x2,
                                                       X1_ROWS, 256, 384);
    // L3: [262144,64] @ w2^T[64,128]
    mma_gemm<3><<<dim3(128 / BN, X2_ROWS / BM), 256>>>(x2, w2b, b2, x3,
                                                       X2_ROWS, 128, 64);
    // L4
    layer4_kernel<<<X3_ROWS / 256, 256>>>(x3, w3, b3, out);
}